// round 5
// baseline (speedup 1.0000x reference)
#include <cuda_runtime.h>

#define NN 2048
#define DD 8
#define HH 64
#define KB 2048          // histogram buckets
#define NTH 1024         // threads per block

// Scratch (no allocation allowed in kernel_launch).
__device__ float g_T[HH * NN];            // (S - D)[h][i]
__device__ unsigned g_cnt = 0;            // monotonic grid-barrier ticket counter

// ---------------------------------------------------------------------------
// Single fused kernel: one block per h (grid = 64 <= #SMs, all co-resident).
// Phase A (per-h): x1/x2 projections, exact histogram CDF table F, per-i
//   relu-sum queries -> g_T[h][:].
// Grid barrier (monotonic ticket counter; graph-replay safe, no reset).
// Phase B: block b produces out rows [32b, 32b+32) = (g_T^T @ W2^T)/(N-1)+b2.
// ---------------------------------------------------------------------------
__global__ void __launch_bounds__(NTH) k_fused(const float* __restrict__ msg,
                                               const float* __restrict__ W1,
                                               const float* __restrict__ b1,
                                               const float* __restrict__ W2,
                                               const float* __restrict__ b2,
                                               float* __restrict__ out) {
    const int h = blockIdx.x;
    __shared__ float w[16];
    __shared__ float cnt[KB];            // reused as red[8][32][8] in phase B
    __shared__ float sum[KB];
    __shared__ float Farr[KB + 1];
    __shared__ float w2s[DD * HH];
    __shared__ float b2s[DD];
    __shared__ float redmin[32], redmax[32];
    __shared__ float wcC[32], wcS[32];
    __shared__ float sh_lo, sh_hi, sh_totC, sh_totS;

    const int t = threadIdx.x;
    const int lane = t & 31;
    const int wid = t >> 5;

    if (t < 16) w[t] = W1[h * 16 + t];
    if (t >= 512 && t < 512 + DD * HH) w2s[t - 512] = W2[t - 512];   // phase-B weights
    if (t >= 256 && t < 256 + DD) b2s[t - 256] = b2[t - 256];
    const float b1h = __ldg(&b1[h]);
    // zero histogram
    cnt[t] = 0.0f; cnt[t + NTH] = 0.0f;
    sum[t] = 0.0f; sum[t + NTH] = 0.0f;
    __syncthreads();  // (1) w ready, hist zeroed

    // two rows per thread
    const int j0 = t, j1 = t + NTH;
    const float4* m0p = reinterpret_cast<const float4*>(msg + j0 * 8);
    const float4* m1p = reinterpret_cast<const float4*>(msg + j1 * 8);
    float4 a0 = m0p[0], a1 = m0p[1];
    float4 c0 = m1p[0], c1 = m1p[1];

    float x1_0 = a0.x*w[0]+a0.y*w[1]+a0.z*w[2]+a0.w*w[3]
               + a1.x*w[4]+a1.y*w[5]+a1.z*w[6]+a1.w*w[7];
    float x2_0 = a0.x*w[8]+a0.y*w[9]+a0.z*w[10]+a0.w*w[11]
               + a1.x*w[12]+a1.y*w[13]+a1.z*w[14]+a1.w*w[15];
    float x1_1 = c0.x*w[0]+c0.y*w[1]+c0.z*w[2]+c0.w*w[3]
               + c1.x*w[4]+c1.y*w[5]+c1.z*w[6]+c1.w*w[7];
    float x2_1 = c0.x*w[8]+c0.y*w[9]+c0.z*w[10]+c0.w*w[11]
               + c1.x*w[12]+c1.y*w[13]+c1.z*w[14]+c1.w*w[15];

    // block min/max of x2
    float mn = fminf(x2_0, x2_1), mx = fmaxf(x2_0, x2_1);
#pragma unroll
    for (int o = 16; o >= 1; o >>= 1) {
        mn = fminf(mn, __shfl_xor_sync(0xffffffffu, mn, o));
        mx = fmaxf(mx, __shfl_xor_sync(0xffffffffu, mx, o));
    }
    if (lane == 0) { redmin[wid] = mn; redmax[wid] = mx; }
    __syncthreads();  // (2)
    if (t < 32) {
        float m2 = redmin[t], x2m = redmax[t];
#pragma unroll
        for (int o = 16; o >= 1; o >>= 1) {
            m2 = fminf(m2, __shfl_xor_sync(0xffffffffu, m2, o));
            x2m = fmaxf(x2m, __shfl_xor_sync(0xffffffffu, x2m, o));
        }
        if (t == 0) { sh_lo = m2; sh_hi = x2m; }
    }
    __syncthreads();  // (3)

    const float lo = sh_lo, hi = sh_hi;
    const float range = fmaxf(hi - lo, 1e-30f);
    const float invD = (float)KB / range;
    const float Delta = range / (float)KB;

    // histogram (smem float atomics; spread addresses)
    int bi0 = (int)((x2_0 - lo) * invD); bi0 = bi0 > KB - 1 ? KB - 1 : (bi0 < 0 ? 0 : bi0);
    int bi1 = (int)((x2_1 - lo) * invD); bi1 = bi1 > KB - 1 ? KB - 1 : (bi1 < 0 ? 0 : bi1);
    atomicAdd(&cnt[bi0], 1.0f); atomicAdd(&sum[bi0], x2_0);
    atomicAdd(&cnt[bi1], 1.0f); atomicAdd(&sum[bi1], x2_1);
    __syncthreads();  // (4)

    // block prefix scan over bucket pairs (channels: cnt, sum)
    float pc0 = cnt[2 * t], pc1 = cnt[2 * t + 1];
    float ps0 = sum[2 * t], ps1 = sum[2 * t + 1];
    float csum = pc0 + pc1, ssum = ps0 + ps1;
    float cI = csum, sI = ssum;
#pragma unroll
    for (int o = 1; o < 32; o <<= 1) {
        float nc = __shfl_up_sync(0xffffffffu, cI, o);
        float ns = __shfl_up_sync(0xffffffffu, sI, o);
        if (lane >= o) { cI += nc; sI += ns; }
    }
    if (lane == 31) { wcC[wid] = cI; wcS[wid] = sI; }
    __syncthreads();  // (5)
    if (t < 32) {
        float oc = wcC[t], os = wcS[t];
        float ocI = oc, osI = os;
#pragma unroll
        for (int o = 1; o < 32; o <<= 1) {
            float nc = __shfl_up_sync(0xffffffffu, ocI, o);
            float ns = __shfl_up_sync(0xffffffffu, osI, o);
            if (t >= o) { ocI += nc; osI += ns; }
        }
        wcC[t] = ocI - oc;  // exclusive warp offsets
        wcS[t] = osI - os;
        if (t == 31) { sh_totC = ocI; sh_totS = osI; }
    }
    __syncthreads();  // (6)

    const float totC = sh_totC, totS = sh_totS;
    float exC = wcC[wid] + (cI - csum);   // exclusive prefix before bucket 2t
    float exS = wcS[wid] + (sI - ssum);

    // F[b] = sumAbove[b] - thr_b * cntAbove[b]   (exact at edges)
    {
        float cAb0 = totC - exC;
        float sAb0 = totS - exS;
        float cAb1 = cAb0 - pc0;
        float sAb1 = sAb0 - ps0;
        float thr0 = lo + (float)(2 * t) * Delta;
        float thr1 = lo + (float)(2 * t + 1) * Delta;
        Farr[2 * t]     = sAb0 - thr0 * cAb0;
        Farr[2 * t + 1] = sAb1 - thr1 * cAb1;
        if (t == 0) Farr[KB] = 0.0f;
    }
    __syncthreads();  // (7)

    // queries -> g_T[h][:]
#pragma unroll
    for (int r = 0; r < 2; r++) {
        float x1v = r ? x1_1 : x1_0;
        float x2v = r ? x2_1 : x2_0;
        int j = r ? j1 : j0;
        float a = x1v + b1h;
        float thr = -a;
        float f;
        if (thr < lo) {
            f = totS - thr * (float)NN;           // exact: all elements active
        } else if (thr >= hi) {
            f = 0.0f;                              // exact: none active
        } else {
            float u = (thr - lo) * invD;
            int b = (int)u; b = b > KB - 1 ? KB - 1 : b;
            float frac = u - (float)b;
            float f0 = Farr[b], f1 = Farr[b + 1];
            f = f0 + frac * (f1 - f0);
        }
        float Dg = fmaxf(a + x2v, 0.0f);
        g_T[h * NN + j] = f - Dg;
    }

    // ---- grid barrier (monotonic ticket; all 64 CTAs co-resident) ----
    __syncthreads();   // all g_T stores issued
    if (t == 0) {
        __threadfence();                                  // publish g_T
        unsigned ticket = atomicAdd(&g_cnt, 1u) + 1u;
        unsigned target = ((ticket - 1u) | 63u) + 1u;     // next multiple of 64
        unsigned v;
        do {
            asm volatile("ld.global.acquire.gpu.u32 %0, [%1];"
                         : "=r"(v) : "l"(&g_cnt));
        } while (v < target);
    }
    __syncthreads();   // release to whole block

    // ---- Phase B: out rows [32*blk, 32*blk+32) ----
    // red[wid][lane][d] aliased onto cnt (8 warps * 32 * 8 = 2048 floats)
    float (*red)[32][DD] = reinterpret_cast<float (*)[32][DD]>(cnt);
    const int base_i = blockIdx.x * 32;

    if (t < 256) {
        float acc[DD];
#pragma unroll
        for (int d = 0; d < DD; d++) acc[d] = 0.0f;
#pragma unroll
        for (int k = 0; k < 8; k++) {
            const int hh = wid * 8 + k;
            float v = g_T[hh * NN + base_i + lane];
#pragma unroll
            for (int d = 0; d < DD; d++) acc[d] += v * w2s[d * HH + hh];
        }
#pragma unroll
        for (int d = 0; d < DD; d++) red[wid][lane][d] = acc[d];
    }
    __syncthreads();

    if (t < 256) {
        const int il = t >> 3, d = t & 7;
        float s = 0.0f;
#pragma unroll
        for (int wdx = 0; wdx < 8; wdx++) s += red[wdx][il][d];
        out[base_i * DD + t] = s * (1.0f / (float)(NN - 1)) + b2s[d];
    }
}

// ---------------------------------------------------------------------------
extern "C" void kernel_launch(void* const* d_in, const int* in_sizes, int n_in,
                              void* d_out, int out_size) {
    // Identify inputs by element count (all distinct): robust to ordering.
    const float* msg = nullptr;  // 2048*8   = 16384
    const float* W1  = nullptr;  // 64*16    = 1024
    const float* b1  = nullptr;  // 64
    const float* W2  = nullptr;  // 8*64     = 512
    const float* b2  = nullptr;  // 8
    for (int k = 0; k < n_in; k++) {
        switch (in_sizes[k]) {
            case 16384: msg = (const float*)d_in[k]; break;
            case 1024:  W1  = (const float*)d_in[k]; break;
            case 64:    b1  = (const float*)d_in[k]; break;
            case 512:   W2  = (const float*)d_in[k]; break;
            case 8:     b2  = (const float*)d_in[k]; break;
            default: break;
        }
    }
    float* out = (float*)d_out;

    k_fused<<<HH, NTH>>>(msg, W1, b1, W2, b2, out);
}

// round 6
// speedup vs baseline: 1.0238x; 1.0238x over previous
#include <cuda_runtime.h>

#define NN 2048
#define DD 8
#define HH 64
#define KB 512           // histogram buckets
#define NTH 1024         // threads per block

// Scratch (no allocation allowed in kernel_launch).
__device__ float g_T[HH * NN];            // (S - D)[h][i]
__device__ unsigned g_cnt = 0;            // monotonic grid-barrier ticket counter

// Order-preserving float <-> uint map (for atomicMin/Max on floats)
__device__ __forceinline__ unsigned fenc(float f) {
    unsigned u = __float_as_uint(f);
    return (u & 0x80000000u) ? ~u : (u | 0x80000000u);
}
__device__ __forceinline__ float fdec(unsigned e) {
    return (e & 0x80000000u) ? __uint_as_float(e ^ 0x80000000u)
                             : __uint_as_float(~e);
}

// ---------------------------------------------------------------------------
// One fused kernel: block = one h (grid 64, all co-resident).
// Phase A: projections -> exact histogram CDF table F (512 bins) -> per-i
//          relu-sum queries -> g_T[h][:].   (4 block barriers)
// Grid barrier (monotonic ticket; graph-replay safe).
// Phase B: block b emits out rows [32b, 32b+32).
// ---------------------------------------------------------------------------
__global__ void __launch_bounds__(NTH) k_fused(const float* __restrict__ msg,
                                               const float* __restrict__ W1,
                                               const float* __restrict__ b1,
                                               const float* __restrict__ W2,
                                               const float* __restrict__ b2,
                                               float* __restrict__ out) {
    const int h = blockIdx.x;
    __shared__ __align__(16) float w[16];
    __shared__ __align__(16) float w2s[DD * HH];
    __shared__ __align__(16) float b2s[DD];
    __shared__ __align__(16) float cnt[KB];
    __shared__ __align__(16) float sum[KB];
    __shared__ __align__(16) float Farr[KB + 1];
    __shared__ __align__(16) float red[8][32][DD];
    __shared__ unsigned sh_lo_u, sh_hi_u;
    __shared__ float sh_totS;

    const int t = threadIdx.x;
    const int lane = t & 31;
    const int wid = t >> 5;

    // Prefetch message rows (independent of smem) to hide latency behind B0.
    const int j0 = t, j1 = t + NTH;
    const float4* m0p = reinterpret_cast<const float4*>(msg + j0 * 8);
    const float4* m1p = reinterpret_cast<const float4*>(msg + j1 * 8);
    float4 a0 = m0p[0], a1 = m0p[1];
    float4 c0 = m1p[0], c1 = m1p[1];

    if (t < 16) w[t] = W1[h * 16 + t];
    if (t >= 32 && t < 32 + DD * HH) w2s[t - 32] = W2[t - 32];
    if (t >= 544 && t < 544 + DD) b2s[t - 544] = b2[t - 544];
    if (t == 1023) { sh_lo_u = 0xFFFFFFFFu; sh_hi_u = 0u; }
    if (t < KB) { cnt[t] = 0.0f; sum[t] = 0.0f; }
    const float b1h = __ldg(&b1[h]);
    __syncthreads();  // B0: w ready, hist zeroed, lo/hi init

    float x1_0 = a0.x*w[0]+a0.y*w[1]+a0.z*w[2]+a0.w*w[3]
               + a1.x*w[4]+a1.y*w[5]+a1.z*w[6]+a1.w*w[7];
    float x2_0 = a0.x*w[8]+a0.y*w[9]+a0.z*w[10]+a0.w*w[11]
               + a1.x*w[12]+a1.y*w[13]+a1.z*w[14]+a1.w*w[15];
    float x1_1 = c0.x*w[0]+c0.y*w[1]+c0.z*w[2]+c0.w*w[3]
               + c1.x*w[4]+c1.y*w[5]+c1.z*w[6]+c1.w*w[7];
    float x2_1 = c0.x*w[8]+c0.y*w[9]+c0.z*w[10]+c0.w*w[11]
               + c1.x*w[12]+c1.y*w[13]+c1.z*w[14]+c1.w*w[15];

    // warp min/max of x2, one atomic per warp
    float mn = fminf(x2_0, x2_1), mx = fmaxf(x2_0, x2_1);
#pragma unroll
    for (int o = 16; o >= 1; o >>= 1) {
        mn = fminf(mn, __shfl_xor_sync(0xffffffffu, mn, o));
        mx = fmaxf(mx, __shfl_xor_sync(0xffffffffu, mx, o));
    }
    if (lane == 0) {
        atomicMin(&sh_lo_u, fenc(mn));
        atomicMax(&sh_hi_u, fenc(mx));
    }
    __syncthreads();  // B1: lo/hi final

    const float lo = fdec(sh_lo_u), hi = fdec(sh_hi_u);
    const float range = fmaxf(hi - lo, 1e-30f);
    const float invD = (float)KB / range;
    const float Delta = range / (float)KB;

    // histogram (smem float atomics)
    int bi0 = (int)((x2_0 - lo) * invD); bi0 = bi0 > KB - 1 ? KB - 1 : (bi0 < 0 ? 0 : bi0);
    int bi1 = (int)((x2_1 - lo) * invD); bi1 = bi1 > KB - 1 ? KB - 1 : (bi1 < 0 ? 0 : bi1);
    atomicAdd(&cnt[bi0], 1.0f); atomicAdd(&sum[bi0], x2_0);
    atomicAdd(&cnt[bi1], 1.0f); atomicAdd(&sum[bi1], x2_1);
    __syncthreads();  // B2: hist final

    // warp 0: register scan of 512 buckets (16/lane) -> Farr
    if (wid == 0) {
        float c[16], s[16];
        const float4* c4 = reinterpret_cast<const float4*>(cnt) + lane * 4;
        const float4* s4 = reinterpret_cast<const float4*>(sum) + lane * 4;
#pragma unroll
        for (int q = 0; q < 4; q++) {
            float4 cc = c4[q], ss = s4[q];
            c[q*4+0]=cc.x; c[q*4+1]=cc.y; c[q*4+2]=cc.z; c[q*4+3]=cc.w;
            s[q*4+0]=ss.x; s[q*4+1]=ss.y; s[q*4+2]=ss.z; s[q*4+3]=ss.w;
        }
        float ctot = 0.0f, stot = 0.0f;
#pragma unroll
        for (int k = 0; k < 16; k++) { ctot += c[k]; stot += s[k]; }
        float cI = ctot, sI = stot;
#pragma unroll
        for (int o = 1; o < 32; o <<= 1) {
            float nc = __shfl_up_sync(0xffffffffu, cI, o);
            float ns = __shfl_up_sync(0xffffffffu, sI, o);
            if (lane >= o) { cI += nc; sI += ns; }
        }
        const float totS = __shfl_sync(0xffffffffu, sI, 31);
        if (lane == 31) sh_totS = totS;
        float pc = cI - ctot, ps = sI - stot;   // exclusive prefix before chunk
        float Fv[16];
#pragma unroll
        for (int k = 0; k < 16; k++) {
            float thr = lo + (float)(16 * lane + k) * Delta;
            Fv[k] = (totS - ps) - thr * ((float)NN - pc);
            pc += c[k]; ps += s[k];
        }
        float4* F4 = reinterpret_cast<float4*>(Farr) + lane * 4;
#pragma unroll
        for (int q = 0; q < 4; q++) {
            F4[q] = make_float4(Fv[q*4+0], Fv[q*4+1], Fv[q*4+2], Fv[q*4+3]);
        }
        if (lane == 31) Farr[KB] = 0.0f;
    }
    __syncthreads();  // B3: F ready

    const float totS = sh_totS;

    // queries -> g_T[h][:]
#pragma unroll
    for (int r = 0; r < 2; r++) {
        float x1v = r ? x1_1 : x1_0;
        float x2v = r ? x2_1 : x2_0;
        int j = r ? j1 : j0;
        float a = x1v + b1h;
        float thr = -a;
        float f;
        if (thr < lo) {
            f = totS - thr * (float)NN;           // exact: all elements active
        } else if (thr >= hi) {
            f = 0.0f;                              // exact: none active
        } else {
            float u = (thr - lo) * invD;
            int b = (int)u; b = b > KB - 1 ? KB - 1 : b;
            float frac = u - (float)b;
            float f0 = Farr[b], f1 = Farr[b + 1];
            f = f0 + frac * (f1 - f0);
        }
        float Dg = fmaxf(a + x2v, 0.0f);
        g_T[h * NN + j] = f - Dg;
    }

    // ---- grid barrier (monotonic ticket; all 64 CTAs co-resident) ----
    __syncthreads();   // all g_T stores issued
    if (t == 0) {
        __threadfence();                                  // publish g_T
        unsigned ticket = atomicAdd(&g_cnt, 1u) + 1u;
        unsigned target = ((ticket - 1u) | 63u) + 1u;     // next multiple of 64
        unsigned v;
        do {
            asm volatile("ld.global.acquire.gpu.u32 %0, [%1];"
                         : "=r"(v) : "l"(&g_cnt));
        } while (v < target);
    }
    __syncthreads();   // release to whole block

    // ---- Phase B: out rows [32*blk, 32*blk+32) ----
    const int base_i = blockIdx.x * 32;
    if (t < 256) {
        float acc[DD];
#pragma unroll
        for (int d = 0; d < DD; d++) acc[d] = 0.0f;
#pragma unroll
        for (int k = 0; k < 8; k++) {
            const int hh = wid * 8 + k;
            float v = g_T[hh * NN + base_i + lane];
#pragma unroll
            for (int d = 0; d < DD; d++) acc[d] += v * w2s[d * HH + hh];
        }
#pragma unroll
        for (int d = 0; d < DD; d++) red[wid][lane][d] = acc[d];
    }
    __syncthreads();

    if (t < 256) {
        const int il = t >> 3, d = t & 7;
        float s = 0.0f;
#pragma unroll
        for (int wdx = 0; wdx < 8; wdx++) s += red[wdx][il][d];
        out[base_i * DD + t] = s * (1.0f / (float)(NN - 1)) + b2s[d];
    }
}

// ---------------------------------------------------------------------------
extern "C" void kernel_launch(void* const* d_in, const int* in_sizes, int n_in,
                              void* d_out, int out_size) {
    // Identify inputs by element count (all distinct): robust to ordering.
    const float* msg = nullptr;  // 2048*8   = 16384
    const float* W1  = nullptr;  // 64*16    = 1024
    const float* b1  = nullptr;  // 64
    const float* W2  = nullptr;  // 8*64     = 512
    const float* b2  = nullptr;  // 8
    for (int k = 0; k < n_in; k++) {
        switch (in_sizes[k]) {
            case 16384: msg = (const float*)d_in[k]; break;
            case 1024:  W1  = (const float*)d_in[k]; break;
            case 64:    b1  = (const float*)d_in[k]; break;
            case 512:   W2  = (const float*)d_in[k]; break;
            case 8:     b2  = (const float*)d_in[k]; break;
            default: break;
        }
    }
    float* out = (float*)d_out;

    k_fused<<<HH, NTH>>>(msg, W1, b1, W2, b2, out);
}